// round 3
// baseline (speedup 1.0000x reference)
#include <cuda_runtime.h>

#define NN 50000
#define CC 128
#define NE 800000

// Scratch (device globals: allocation-free rule)
__device__ float  g_dinv[NN];
__device__ float4 g_h[NN * 32];     // current dense transform  [NN][128]
__device__ float4 g_agg[NN * 32];   // aggregation accumulator  [NN][128]
__device__ float4 g_feat[NN * 32];  // layer output / embedding [NN][128]

// ---------------- degree / normalization ----------------

__global__ void deg_init_kernel() {
    int i = blockIdx.x * blockDim.x + threadIdx.x;
    if (i < NN) g_dinv[i] = 1.0f;   // self loop
}

__global__ void deg_accum_kernel(const int* __restrict__ ei) {
    int e = blockIdx.x * blockDim.x + threadIdx.x;
    if (e < NE) atomicAdd(&g_dinv[ei[e]], 1.0f);
}

__global__ void deg_rsqrt_kernel() {
    int i = blockIdx.x * blockDim.x + threadIdx.x;
    if (i < NN) g_dinv[i] = rsqrtf(g_dinv[i]);   // deg >= 1 always
}

// ---------------- aggregation ----------------

// agg[i] = h[i] * dinv[node]^2   (self-loop contribution, non-atomic init)
__global__ void init_agg_kernel() {
    int i = blockIdx.x * blockDim.x + threadIdx.x;
    if (i >= NN * 32) return;
    int node = i >> 5;
    float d = g_dinv[node];
    float s = d * d;
    float4 v = g_h[i];
    v.x *= s; v.y *= s; v.z *= s; v.w *= s;
    g_agg[i] = v;
}

// one warp per edge: gather h[col]*norm, red.add into agg[row]
__global__ void edge_agg_kernel(const int* __restrict__ ei) {
    int gw = (blockIdx.x * blockDim.x + threadIdx.x) >> 5;
    int lane = threadIdx.x & 31;
    if (gw >= NE) return;
    int r = ei[gw];
    int c = ei[NE + gw];
    float norm = g_dinv[r] * g_dinv[c];
    float4 v = g_h[c * 32 + lane];
    v.x *= norm; v.y *= norm; v.z *= norm; v.w *= norm;
    float* dst = (float*)g_agg + (size_t)r * CC + lane * 4;
    asm volatile("red.global.add.v4.f32 [%0], {%1,%2,%3,%4};"
                 :: "l"(dst), "f"(v.x), "f"(v.y), "f"(v.z), "f"(v.w)
                 : "memory");
}

// feat[i] = (agg[i] + bias[ch])  [+ relu]
template <int RELU>
__global__ void finalize_kernel(const float* __restrict__ bias) {
    int i = blockIdx.x * blockDim.x + threadIdx.x;
    if (i >= NN * 32) return;
    int ch4 = i & 31;
    float4 a = g_agg[i];
    float4 b = ((const float4*)bias)[ch4];
    a.x += b.x; a.y += b.y; a.z += b.z; a.w += b.w;
    if (RELU) {
        a.x = fmaxf(a.x, 0.f); a.y = fmaxf(a.y, 0.f);
        a.z = fmaxf(a.z, 0.f); a.w = fmaxf(a.w, 0.f);
    }
    g_feat[i] = a;
}

// ---------------- generic K=128 fp32 GEMM: C[M,N] = A[M,128] @ W[128,N] (+bias) ----------------
// BM=128, BN=128 tiles, K chunked by 64, 256 threads, 8x8 register tile per thread.

__global__ __launch_bounds__(256) void gemm_k128_kernel(
    const float* __restrict__ A, const float* __restrict__ W,
    const float* __restrict__ bias, float* __restrict__ Cmat,
    int M, int N)
{
    __shared__ float As[128 * 64];   // As[m][k]  (row-major; broadcast scalar reads)
    __shared__ float Bs[64 * 128];   // Bs[k][n]

    const int bm = blockIdx.y * 128;
    const int bn = blockIdx.x * 128;
    const int tid = threadIdx.x;
    const int tr = (tid >> 4) << 3;   // row offset 0..120
    const int tc = (tid & 15) << 3;   // col offset 0..120
    const bool n_vec = ((N & 3) == 0);  // float4 path only if row stride is 16B-aligned

    float acc[8][8];
#pragma unroll
    for (int i = 0; i < 8; i++)
#pragma unroll
        for (int j = 0; j < 8; j++) acc[i][j] = 0.f;

    for (int kc = 0; kc < 128; kc += 64) {
        // load A chunk: 128 rows x 64 k = 2048 float4 (coalesced, conflict-free stores)
        for (int i = tid; i < 2048; i += 256) {
            int m  = i >> 4;        // 0..127
            int k4 = i & 15;        // float4 index within 64-k chunk
            int gm = bm + m;
            float4 v = make_float4(0.f, 0.f, 0.f, 0.f);
            if (gm < M) v = ((const float4*)(A + (size_t)gm * 128 + kc))[k4];
            ((float4*)As)[m * 16 + k4] = v;
        }
        // load B chunk: 64 k-rows x 128 cols
        for (int i = tid; i < 2048; i += 256) {
            int k  = i >> 5;        // 0..63
            int n4 = (i & 31) << 2; // col 0..124 step 4
            int gn = bn + n4;
            int gk = kc + k;
            float4 v;
            if (n_vec && gn + 3 < N) {
                v = *(const float4*)(W + (size_t)gk * N + gn);
            } else {
                v.x = (gn + 0 < N) ? W[(size_t)gk * N + gn + 0] : 0.f;
                v.y = (gn + 1 < N) ? W[(size_t)gk * N + gn + 1] : 0.f;
                v.z = (gn + 2 < N) ? W[(size_t)gk * N + gn + 2] : 0.f;
                v.w = (gn + 3 < N) ? W[(size_t)gk * N + gn + 3] : 0.f;
            }
            *(float4*)(Bs + k * 128 + n4) = v;
        }
        __syncthreads();

#pragma unroll 8
        for (int k = 0; k < 64; k++) {
            float a[8], b[8];
#pragma unroll
            for (int i = 0; i < 8; i++) a[i] = As[(tr + i) * 64 + k];  // broadcast
            float4 b0 = *(const float4*)(Bs + k * 128 + tc);
            float4 b1 = *(const float4*)(Bs + k * 128 + tc + 4);
            b[0] = b0.x; b[1] = b0.y; b[2] = b0.z; b[3] = b0.w;
            b[4] = b1.x; b[5] = b1.y; b[6] = b1.z; b[7] = b1.w;
#pragma unroll
            for (int i = 0; i < 8; i++)
#pragma unroll
                for (int j = 0; j < 8; j++) acc[i][j] = fmaf(a[i], b[j], acc[i][j]);
        }
        __syncthreads();
    }

    float bv[8];
#pragma unroll
    for (int j = 0; j < 8; j++) {
        int gn = bn + tc + j;
        bv[j] = (bias && gn < N) ? bias[gn] : 0.f;
    }
#pragma unroll
    for (int i = 0; i < 8; i++) {
        int gm = bm + tr + i;
        if (gm >= M) continue;
#pragma unroll
        for (int j = 0; j < 8; j++) {
            int gn = bn + tc + j;
            if (gn < N) Cmat[(size_t)gm * N + gn] = acc[i][j] + bv[j];
        }
    }
}

// ---------------- launch ----------------

extern "C" void kernel_launch(void* const* d_in, const int* in_sizes, int n_in,
                              void* d_out, int out_size) {
    const float* x  = (const float*)d_in[0];
    const int*   ei = (const int*)d_in[1];   // [2, NE] int32
    const float* W1 = (const float*)d_in[2];
    const float* b1 = (const float*)d_in[3];
    const float* W2 = (const float*)d_in[4];
    const float* b2 = (const float*)d_in[5];
    const float* Wt = (const float*)d_in[6];
    const float* bt = (const float*)d_in[7];
    const float* Ws = (const float*)d_in[8];
    const float* bs = (const float*)d_in[9];
    const float* Wf = (const float*)d_in[10];
    const float* bf = (const float*)d_in[11];
    const float* Wa = (const float*)d_in[12];
    const float* ba = (const float*)d_in[13];
    float* out = (float*)d_out;

    float4 *h4, *feat4;
    cudaGetSymbolAddress((void**)&h4, g_h);
    cudaGetSymbolAddress((void**)&feat4, g_feat);
    const float* feat = (const float*)feat4;

    // normalization (shared by both convs)
    deg_init_kernel<<<(NN + 255) / 256, 256>>>();
    deg_accum_kernel<<<(NE + 255) / 256, 256>>>(ei);
    deg_rsqrt_kernel<<<(NN + 255) / 256, 256>>>();

    const int ELEM_BLK = (NN * 32 + 255) / 256;
    const int EDGE_BLK = ((NE * 32) + 255) / 256;
    dim3 gemm_grid_128(1, (NN + 127) / 128);

    // layer 1: h = x@W1; agg = norm-sum; feat = relu(agg + b1)
    gemm_k128_kernel<<<gemm_grid_128, 256>>>(x, W1, nullptr, (float*)h4, NN, 128);
    init_agg_kernel<<<ELEM_BLK, 256>>>();
    edge_agg_kernel<<<EDGE_BLK, 256>>>(ei);
    finalize_kernel<1><<<ELEM_BLK, 256>>>(b1);

    // layer 2: h = feat@W2; agg; emb = agg + b2
    gemm_k128_kernel<<<gemm_grid_128, 256>>>(feat, W2, nullptr, (float*)h4, NN, 128);
    init_agg_kernel<<<ELEM_BLK, 256>>>();
    edge_agg_kernel<<<EDGE_BLK, 256>>>(ei);
    finalize_kernel<0><<<ELEM_BLK, 256>>>(b2);

    // heads (outputs concatenated in tuple order)
    gemm_k128_kernel<<<dim3(1, 391), 256>>>(feat, Wt, bt, out,                    NN, 30);
    gemm_k128_kernel<<<dim3(1, 391), 256>>>(feat, Ws, bs, out + (size_t)NN * 30,  NN, 20);
    gemm_k128_kernel<<<dim3(1, 391), 256>>>(feat, Wf, bf, out + (size_t)NN * 50,  NN, 15);
    gemm_k128_kernel<<<dim3(16, 391), 256>>>(feat, Wa, ba, out + (size_t)NN * 65, NN, 2000);
}

// round 5
// speedup vs baseline: 1.3906x; 1.3906x over previous
#include <cuda_runtime.h>
#include <cuda_bf16.h>
#include <cstdint>

#define NN 50000
#define CC 128
#define NE 800000
#define NAUTH 2000

// ---------------- scratch (device globals; allocation-free rule) ----------------
__device__ float  g_dinv[NN];
__device__ float4 g_h[NN * 32];     // dense transform  [NN][128]
__device__ float4 g_agg[NN * 32];   // aggregation accumulator
__device__ float4 g_feat[NN * 32];  // layer output / embedding
__device__ __nv_bfloat16 g_featH[NN * 128];
__device__ __nv_bfloat16 g_featL[NN * 128];
__device__ __nv_bfloat16 g_WaH[NAUTH * 128];   // Wa transposed, [n][k]
__device__ __nv_bfloat16 g_WaL[NAUTH * 128];
__device__ float g_Wcat[128 * 65];  // concat of Wt|Ws|Wf
__device__ float g_Csmall[NN * 65];

// ---------------- degree / normalization ----------------
__global__ void deg_init_kernel() {
    int i = blockIdx.x * blockDim.x + threadIdx.x;
    if (i < NN) g_dinv[i] = 1.0f;
}
__global__ void deg_accum_kernel(const int* __restrict__ ei) {
    int e = blockIdx.x * blockDim.x + threadIdx.x;
    if (e < NE) atomicAdd(&g_dinv[ei[e]], 1.0f);
}
__global__ void deg_rsqrt_kernel() {
    int i = blockIdx.x * blockDim.x + threadIdx.x;
    if (i < NN) g_dinv[i] = rsqrtf(g_dinv[i]);
}

// ---------------- aggregation ----------------
__global__ void init_agg_kernel() {
    int i = blockIdx.x * blockDim.x + threadIdx.x;
    if (i >= NN * 32) return;
    int node = i >> 5;
    float d = g_dinv[node];
    float s = d * d;
    float4 v = g_h[i];
    v.x *= s; v.y *= s; v.z *= s; v.w *= s;
    g_agg[i] = v;
}
__global__ void edge_agg_kernel(const int* __restrict__ ei) {
    int gw = (blockIdx.x * blockDim.x + threadIdx.x) >> 5;
    int lane = threadIdx.x & 31;
    if (gw >= NE) return;
    int r = ei[gw];
    int c = ei[NE + gw];
    float norm = g_dinv[r] * g_dinv[c];
    float4 v = g_h[c * 32 + lane];
    v.x *= norm; v.y *= norm; v.z *= norm; v.w *= norm;
    float* dst = (float*)g_agg + (size_t)r * CC + lane * 4;
    asm volatile("red.global.add.v4.f32 [%0], {%1,%2,%3,%4};"
                 :: "l"(dst), "f"(v.x), "f"(v.y), "f"(v.z), "f"(v.w) : "memory");
}
template <int RELU>
__global__ void finalize_kernel(const float* __restrict__ bias) {
    int i = blockIdx.x * blockDim.x + threadIdx.x;
    if (i >= NN * 32) return;
    int ch4 = i & 31;
    float4 a = g_agg[i];
    float4 b = ((const float4*)bias)[ch4];
    a.x += b.x; a.y += b.y; a.z += b.z; a.w += b.w;
    if (RELU) {
        a.x = fmaxf(a.x, 0.f); a.y = fmaxf(a.y, 0.f);
        a.z = fmaxf(a.z, 0.f); a.w = fmaxf(a.w, 0.f);
    }
    g_feat[i] = a;
}

// ---------------- bf16 hi/lo conversion ----------------
__global__ void convert_feat_kernel() {
    int i = blockIdx.x * blockDim.x + threadIdx.x;
    if (i >= NN * 128) return;
    float f = ((const float*)g_feat)[i];
    __nv_bfloat16 hi = __float2bfloat16(f);
    g_featH[i] = hi;
    g_featL[i] = __float2bfloat16(f - __bfloat162float(hi));
}
__global__ void convert_Wa_kernel(const float* __restrict__ Wa) {
    int i = blockIdx.x * blockDim.x + threadIdx.x;
    if (i >= NAUTH * 128) return;
    int n = i >> 7, k = i & 127;
    float f = Wa[(size_t)k * NAUTH + n];
    __nv_bfloat16 hi = __float2bfloat16(f);
    g_WaH[i] = hi;
    g_WaL[i] = __float2bfloat16(f - __bfloat162float(hi));
}

// ---------------- small heads: pack + split ----------------
__global__ void pack_small_kernel(const float* __restrict__ Wt, const float* __restrict__ Ws,
                                  const float* __restrict__ Wf) {
    int i = blockIdx.x * blockDim.x + threadIdx.x;
    if (i >= 128 * 65) return;
    int k = i / 65, j = i % 65;
    float v;
    if (j < 30)      v = Wt[(size_t)k * 30 + j];
    else if (j < 50) v = Ws[(size_t)k * 20 + (j - 30)];
    else             v = Wf[(size_t)k * 15 + (j - 50)];
    g_Wcat[i] = v;
}
__global__ void split_small_kernel(const float* __restrict__ bt, const float* __restrict__ bs,
                                   const float* __restrict__ bfb, float* __restrict__ out) {
    int i = blockIdx.x * blockDim.x + threadIdx.x;
    if (i >= NN * 65) return;
    int m = i / 65, j = i % 65;
    float v = g_Csmall[i];
    if (j < 30)      out[(size_t)m * 30 + j] = v + bt[j];
    else if (j < 50) out[(size_t)NN * 30 + (size_t)m * 20 + (j - 30)] = v + bs[j - 30];
    else             out[(size_t)NN * 50 + (size_t)m * 15 + (j - 50)] = v + bfb[j - 50];
}

// ---------------- fp32 GEMM (layers + fused small heads) ----------------
__global__ __launch_bounds__(256) void gemm_k128_kernel(
    const float* __restrict__ A, const float* __restrict__ W,
    const float* __restrict__ bias, float* __restrict__ Cmat, int M, int N)
{
    __shared__ float As[128 * 64];
    __shared__ float Bs[64 * 128];
    const int bm = blockIdx.y * 128;
    const int bn = blockIdx.x * 128;
    const int tid = threadIdx.x;
    const int tr = (tid >> 4) << 3;
    const int tc = (tid & 15) << 3;
    const bool n_vec = ((N & 3) == 0);

    float acc[8][8];
#pragma unroll
    for (int i = 0; i < 8; i++)
#pragma unroll
        for (int j = 0; j < 8; j++) acc[i][j] = 0.f;

    for (int kc = 0; kc < 128; kc += 64) {
        for (int i = tid; i < 2048; i += 256) {
            int m = i >> 4, k4 = i & 15, gm = bm + m;
            float4 v = make_float4(0.f, 0.f, 0.f, 0.f);
            if (gm < M) v = ((const float4*)(A + (size_t)gm * 128 + kc))[k4];
            ((float4*)As)[m * 16 + k4] = v;
        }
        for (int i = tid; i < 2048; i += 256) {
            int k = i >> 5, n4 = (i & 31) << 2, gn = bn + n4, gk = kc + k;
            float4 v;
            if (n_vec && gn + 3 < N) {
                v = *(const float4*)(W + (size_t)gk * N + gn);
            } else {
                v.x = (gn + 0 < N) ? W[(size_t)gk * N + gn + 0] : 0.f;
                v.y = (gn + 1 < N) ? W[(size_t)gk * N + gn + 1] : 0.f;
                v.z = (gn + 2 < N) ? W[(size_t)gk * N + gn + 2] : 0.f;
                v.w = (gn + 3 < N) ? W[(size_t)gk * N + gn + 3] : 0.f;
            }
            *(float4*)(Bs + k * 128 + n4) = v;
        }
        __syncthreads();
#pragma unroll 8
        for (int k = 0; k < 64; k++) {
            float a[8], b[8];
#pragma unroll
            for (int i = 0; i < 8; i++) a[i] = As[(tr + i) * 64 + k];
            float4 b0 = *(const float4*)(Bs + k * 128 + tc);
            float4 b1 = *(const float4*)(Bs + k * 128 + tc + 4);
            b[0] = b0.x; b[1] = b0.y; b[2] = b0.z; b[3] = b0.w;
            b[4] = b1.x; b[5] = b1.y; b[6] = b1.z; b[7] = b1.w;
#pragma unroll
            for (int i = 0; i < 8; i++)
#pragma unroll
                for (int j = 0; j < 8; j++) acc[i][j] = fmaf(a[i], b[j], acc[i][j]);
        }
        __syncthreads();
    }

    float bv[8];
#pragma unroll
    for (int j = 0; j < 8; j++) {
        int gn = bn + tc + j;
        bv[j] = (bias && gn < N) ? bias[gn] : 0.f;
    }
#pragma unroll
    for (int i = 0; i < 8; i++) {
        int gm = bm + tr + i;
        if (gm >= M) continue;
#pragma unroll
        for (int j = 0; j < 8; j++) {
            int gn = bn + tc + j;
            if (gn < N) Cmat[(size_t)gm * N + gn] = acc[i][j] + bv[j];
        }
    }
}

// ---------------- author head: mma.sync bf16 hi/lo split GEMM ----------------
// Per CTA: 128x128 output tile, 8 warps (4 along m x 2 along n), each 32x64.
// 3 passes: Ah*Bh + Ah*Bl + Al*Bh accumulated in fp32.
// SMEM: bf16 tiles with row stride 136 (272B) -> ldmatrix conflict-free.

#define TSTRIDE 136
#define TILE_BYTES (128 * TSTRIDE * 2)   // 34816

__device__ __forceinline__ uint32_t smem_u32(const void* p) {
    uint32_t a;
    asm("{ .reg .u64 t; cvta.to.shared.u64 t, %1; cvt.u32.u64 %0, t; }" : "=r"(a) : "l"(p));
    return a;
}

__device__ __forceinline__ void ldsm_x4(uint32_t* r, uint32_t addr) {
    asm volatile("ldmatrix.sync.aligned.m8n8.x4.shared.b16 {%0,%1,%2,%3}, [%4];"
                 : "=r"(r[0]), "=r"(r[1]), "=r"(r[2]), "=r"(r[3]) : "r"(addr));
}

__device__ __forceinline__ void mma_bf16(float* d, const uint32_t* a, const uint32_t* b) {
    asm volatile(
        "mma.sync.aligned.m16n8k16.row.col.f32.bf16.bf16.f32 "
        "{%0,%1,%2,%3}, {%4,%5,%6,%7}, {%8,%9}, {%0,%1,%2,%3};"
        : "+f"(d[0]), "+f"(d[1]), "+f"(d[2]), "+f"(d[3])
        : "r"(a[0]), "r"(a[1]), "r"(a[2]), "r"(a[3]), "r"(b[0]), "r"(b[1]));
}

__device__ __forceinline__ void load_tile_bf16(char* dst, const __nv_bfloat16* __restrict__ src,
                                               int row0, int rowmax, int tid) {
    for (int i = tid; i < 2048; i += 256) {       // 128 rows x 16 chunks of 16B
        int r = i >> 4;
        int k = (i & 15) << 3;                     // 8 bf16 per chunk
        int gr = row0 + r;
        uint4 v = make_uint4(0, 0, 0, 0);
        if (gr < rowmax) v = *(const uint4*)(src + (size_t)gr * 128 + k);
        *(uint4*)(dst + ((size_t)r * TSTRIDE + k) * 2) = v;
    }
}

__global__ __launch_bounds__(256) void author_gemm_kernel(
    const float* __restrict__ ba, float* __restrict__ outp)
{
    extern __shared__ char smem[];
    char* sAh = smem;
    char* sAl = smem + TILE_BYTES;
    char* sBh = smem + 2 * TILE_BYTES;
    char* sBl = smem + 3 * TILE_BYTES;

    const int tid = threadIdx.x, wid = tid >> 5, lane = tid & 31;
    const int bm = blockIdx.y * 128;
    const int bn = blockIdx.x * 128;
    const int wm = (wid & 3) * 32;    // warp m offset within tile
    const int wn = (wid >> 2) * 64;   // warp n offset within tile

    load_tile_bf16(sAh, g_featH, bm, NN, tid);
    load_tile_bf16(sAl, g_featL, bm, NN, tid);
    load_tile_bf16(sBh, g_WaH, bn, NAUTH, tid);
    load_tile_bf16(sBl, g_WaL, bn, NAUTH, tid);
    __syncthreads();

    float acc[2][8][4];
#pragma unroll
    for (int mt = 0; mt < 2; mt++)
#pragma unroll
        for (int nt = 0; nt < 8; nt++)
#pragma unroll
            for (int q = 0; q < 4; q++) acc[mt][nt][q] = 0.f;

    const uint32_t aBase[3] = { smem_u32(sAh), smem_u32(sAh), smem_u32(sAl) };
    const uint32_t bBase[3] = { smem_u32(sBh), smem_u32(sBl), smem_u32(sBh) };

    // per-lane ldmatrix row addresses (element offsets, x2 bytes later)
    const int a_row = wm + (lane & 15);
    const int a_col8 = (lane >> 4) * 8;
    const int b_row = wn + (lane & 7) + ((lane >> 4) & 1) * 8;
    const int b_col8 = ((lane >> 3) & 1) * 8;

#pragma unroll
    for (int p = 0; p < 3; p++) {
        const uint32_t ab = aBase[p];
        const uint32_t bb = bBase[p];
#pragma unroll
        for (int ks = 0; ks < 8; ks++) {
            uint32_t afr[2][4];
#pragma unroll
            for (int mt = 0; mt < 2; mt++) {
                uint32_t addr = ab + (uint32_t)(((a_row + mt * 16) * TSTRIDE) + ks * 16 + a_col8) * 2;
                ldsm_x4(afr[mt], addr);
            }
            uint32_t bfr[8][2];
#pragma unroll
            for (int np = 0; np < 4; np++) {
                uint32_t r[4];
                uint32_t addr = bb + (uint32_t)(((b_row + np * 16) * TSTRIDE) + ks * 16 + b_col8) * 2;
                ldsm_x4(r, addr);
                bfr[2 * np][0] = r[0]; bfr[2 * np][1] = r[1];
                bfr[2 * np + 1][0] = r[2]; bfr[2 * np + 1][1] = r[3];
            }
#pragma unroll
            for (int mt = 0; mt < 2; mt++)
#pragma unroll
                for (int nt = 0; nt < 8; nt++)
                    mma_bf16(acc[mt][nt], afr[mt], bfr[nt]);
        }
    }

    // epilogue: c0,c1 -> (m, n0), (m, n0+1); c2,c3 -> (m+8, n0..)
    const int g = lane >> 2, t = lane & 3;
#pragma unroll
    for (int mt = 0; mt < 2; mt++) {
        int m0 = bm + wm + mt * 16 + g;
#pragma unroll
        for (int nt = 0; nt < 8; nt++) {
            int n0 = bn + wn + nt * 8 + t * 2;
            if (n0 >= NAUTH) continue;
            float bx = ba[n0], by = ba[n0 + 1];
            if (m0 < NN) {
                float2 o = make_float2(acc[mt][nt][0] + bx, acc[mt][nt][1] + by);
                *(float2*)(outp + (size_t)m0 * NAUTH + n0) = o;
            }
            if (m0 + 8 < NN) {
                float2 o = make_float2(acc[mt][nt][2] + bx, acc[mt][nt][3] + by);
                *(float2*)(outp + (size_t)(m0 + 8) * NAUTH + n0) = o;
            }
        }
    }
}

// ---------------- launch ----------------
extern "C" void kernel_launch(void* const* d_in, const int* in_sizes, int n_in,
                              void* d_out, int out_size) {
    const float* x  = (const float*)d_in[0];
    const int*   ei = (const int*)d_in[1];   // [2, NE] int32
    const float* W1 = (const float*)d_in[2];
    const float* b1 = (const float*)d_in[3];
    const float* W2 = (const float*)d_in[4];
    const float* b2 = (const float*)d_in[5];
    const float* Wt = (const float*)d_in[6];
    const float* bt = (const float*)d_in[7];
    const float* Ws = (const float*)d_in[8];
    const float* bs = (const float*)d_in[9];
    const float* Wf = (const float*)d_in[10];
    const float* bfb = (const float*)d_in[11];
    const float* Wa = (const float*)d_in[12];
    const float* ba = (const float*)d_in[13];
    float* out = (float*)d_out;

    float4 *h4, *feat4;
    float *csmall, *wcat;
    cudaGetSymbolAddress((void**)&h4, g_h);
    cudaGetSymbolAddress((void**)&feat4, g_feat);
    cudaGetSymbolAddress((void**)&csmall, g_Csmall);
    cudaGetSymbolAddress((void**)&wcat, g_Wcat);
    const float* feat = (const float*)feat4;

    static bool attr_set = false;
    if (!attr_set) {
        cudaFuncSetAttribute(author_gemm_kernel,
                             cudaFuncAttributeMaxDynamicSharedMemorySize, 4 * TILE_BYTES);
        attr_set = true;
    }

    // normalization
    deg_init_kernel<<<(NN + 255) / 256, 256>>>();
    deg_accum_kernel<<<(NE + 255) / 256, 256>>>(ei);
    deg_rsqrt_kernel<<<(NN + 255) / 256, 256>>>();

    // weight conversions (independent of feat)
    convert_Wa_kernel<<<(NAUTH * 128 + 255) / 256, 256>>>(Wa);
    pack_small_kernel<<<(128 * 65 + 255) / 256, 256>>>(Wt, Ws, Wf);

    const int ELEM_BLK = (NN * 32 + 255) / 256;
    const int EDGE_BLK = ((NE * 32) + 255) / 256;
    dim3 gemm_grid_128(1, (NN + 127) / 128);

    // layer 1
    gemm_k128_kernel<<<gemm_grid_128, 256>>>(x, W1, nullptr, (float*)h4, NN, 128);
    init_agg_kernel<<<ELEM_BLK, 256>>>();
    edge_agg_kernel<<<EDGE_BLK, 256>>>(ei);
    finalize_kernel<1><<<ELEM_BLK, 256>>>(b1);

    // layer 2
    gemm_k128_kernel<<<gemm_grid_128, 256>>>(feat, W2, nullptr, (float*)h4, NN, 128);
    init_agg_kernel<<<ELEM_BLK, 256>>>();
    edge_agg_kernel<<<EDGE_BLK, 256>>>(ei);
    finalize_kernel<0><<<ELEM_BLK, 256>>>(b2);

    // embedding -> bf16 hi/lo
    convert_feat_kernel<<<(NN * 128 + 255) / 256, 256>>>();

    // small heads fused: C = feat @ Wcat, then split + bias
    gemm_k128_kernel<<<dim3(1, 391), 256>>>(feat, wcat, nullptr, csmall, NN, 65);
    split_small_kernel<<<(NN * 65 + 255) / 256, 256>>>(bt, bs, bfb, out);

    // author head: tensor cores via mma.sync
    author_gemm_kernel<<<dim3((NAUTH + 127) / 128, (NN + 127) / 128), 256, 4 * TILE_BYTES>>>(
        ba, out + (size_t)NN * 65);
}

// round 7
// speedup vs baseline: 1.5369x; 1.1052x over previous
#include <cuda_runtime.h>
#include <cuda_bf16.h>
#include <cstdint>

#define NN 50000
#define CC 128
#define NE 800000
#define NAUTH 2000
#define NSMALL 65

// ---------------- scratch (device globals; allocation-free rule) ----------------
__device__ float  g_dinv[NN];
__device__ float4 g_h[NN * 32];      // dense transform  [NN][128]
__device__ float4 g_agg[NN * 32];    // aggregation accumulator
__device__ __nv_bfloat16 g_AH[NN * 128];     // A operand hi (x, then relu(h1), then emb)
__device__ __nv_bfloat16 g_AL[NN * 128];     // A operand lo
__device__ __nv_bfloat16 g_WaH[NAUTH * 128]; // Wa^T  [n][k] hi/lo
__device__ __nv_bfloat16 g_WaL[NAUTH * 128];
__device__ __nv_bfloat16 g_W1H[128 * 128];   // W1^T
__device__ __nv_bfloat16 g_W1L[128 * 128];
__device__ __nv_bfloat16 g_W2H[128 * 128];   // W2^T
__device__ __nv_bfloat16 g_W2L[128 * 128];
__device__ __nv_bfloat16 g_WsmH[NSMALL * 128]; // concat(Wt|Ws|Wf)^T
__device__ __nv_bfloat16 g_WsmL[NSMALL * 128];
__device__ float g_Csmall[NN * NSMALL];

// ---------------- degree / normalization ----------------
__global__ void deg_init_kernel() {
    int i = blockIdx.x * blockDim.x + threadIdx.x;
    if (i < NN) g_dinv[i] = 1.0f;
}
__global__ void deg_accum_kernel(const int* __restrict__ ei) {
    int e = blockIdx.x * blockDim.x + threadIdx.x;
    if (e < NE) atomicAdd(&g_dinv[ei[e]], 1.0f);
}
__global__ void deg_rsqrt_kernel() {
    int i = blockIdx.x * blockDim.x + threadIdx.x;
    if (i < NN) g_dinv[i] = rsqrtf(g_dinv[i]);
}

// ---------------- aggregation ----------------
__global__ void init_agg_kernel() {
    int i = blockIdx.x * blockDim.x + threadIdx.x;
    if (i >= NN * 32) return;
    int node = i >> 5;
    float d = g_dinv[node];
    float s = d * d;
    float4 v = g_h[i];
    v.x *= s; v.y *= s; v.z *= s; v.w *= s;
    g_agg[i] = v;
}
__global__ void edge_agg_kernel(const int* __restrict__ ei) {
    int gw = (blockIdx.x * blockDim.x + threadIdx.x) >> 5;
    int lane = threadIdx.x & 31;
    if (gw >= NE) return;
    int r = ei[gw];
    int c = ei[NE + gw];
    float norm = g_dinv[r] * g_dinv[c];
    float4 v = g_h[c * 32 + lane];
    v.x *= norm; v.y *= norm; v.z *= norm; v.w *= norm;
    float* dst = (float*)g_agg + (size_t)r * CC + lane * 4;
    asm volatile("red.global.add.v4.f32 [%0], {%1,%2,%3,%4};"
                 :: "l"(dst), "f"(v.x), "f"(v.y), "f"(v.z), "f"(v.w) : "memory");
}

// finalize: add bias [+relu], write bf16 hi/lo operand directly (fused conversion)
template <int RELU>
__global__ void finalize_kernel(const float* __restrict__ bias) {
    int i = blockIdx.x * blockDim.x + threadIdx.x;
    if (i >= NN * 32) return;
    int ch4 = i & 31;
    float4 a = g_agg[i];
    float4 b = ((const float4*)bias)[ch4];
    a.x += b.x; a.y += b.y; a.z += b.z; a.w += b.w;
    if (RELU) {
        a.x = fmaxf(a.x, 0.f); a.y = fmaxf(a.y, 0.f);
        a.z = fmaxf(a.z, 0.f); a.w = fmaxf(a.w, 0.f);
    }
    float f[4] = {a.x, a.y, a.z, a.w};
    __nv_bfloat16 hi[4], lo[4];
#pragma unroll
    for (int q = 0; q < 4; q++) {
        hi[q] = __float2bfloat16(f[q]);
        lo[q] = __float2bfloat16(f[q] - __bfloat162float(hi[q]));
    }
    *(uint2*)(g_AH + (size_t)i * 4) = *(uint2*)hi;
    *(uint2*)(g_AL + (size_t)i * 4) = *(uint2*)lo;
}

// ---------------- conversions ----------------
__global__ void convert_x_kernel(const float* __restrict__ x) {
    int i = blockIdx.x * blockDim.x + threadIdx.x;
    if (i >= NN * 128) return;
    float f = x[i];
    __nv_bfloat16 hi = __float2bfloat16(f);
    g_AH[i] = hi;
    g_AL[i] = __float2bfloat16(f - __bfloat162float(hi));
}
// generic W[k][n] (k-major, 128 x N) -> dst[n][k] hi/lo
__global__ void convert_W_kernel(const float* __restrict__ W, int N,
                                 __nv_bfloat16* __restrict__ dH, __nv_bfloat16* __restrict__ dL) {
    int i = blockIdx.x * blockDim.x + threadIdx.x;
    if (i >= N * 128) return;
    int n = i >> 7, k = i & 127;
    float f = W[(size_t)k * N + n];
    __nv_bfloat16 hi = __float2bfloat16(f);
    dH[i] = hi;
    dL[i] = __float2bfloat16(f - __bfloat162float(hi));
}
// concat(Wt|Ws|Wf)^T -> g_WsmH/L [65][128]
__global__ void pack_small_kernel(const float* __restrict__ Wt, const float* __restrict__ Ws,
                                  const float* __restrict__ Wf) {
    int i = blockIdx.x * blockDim.x + threadIdx.x;
    if (i >= NSMALL * 128) return;
    int j = i >> 7, k = i & 127;
    float v;
    if (j < 30)      v = Wt[(size_t)k * 30 + j];
    else if (j < 50) v = Ws[(size_t)k * 20 + (j - 30)];
    else             v = Wf[(size_t)k * 15 + (j - 50)];
    __nv_bfloat16 hi = __float2bfloat16(v);
    g_WsmH[i] = hi;
    g_WsmL[i] = __float2bfloat16(v - __bfloat162float(hi));
}
__global__ void split_small_kernel(const float* __restrict__ bt, const float* __restrict__ bs,
                                   const float* __restrict__ bfb, float* __restrict__ out) {
    int i = blockIdx.x * blockDim.x + threadIdx.x;
    if (i >= NN * NSMALL) return;
    int m = i / NSMALL, j = i % NSMALL;
    float v = g_Csmall[i];
    if (j < 30)      out[(size_t)m * 30 + j] = v + bt[j];
    else if (j < 50) out[(size_t)NN * 30 + (size_t)m * 20 + (j - 30)] = v + bs[j - 30];
    else             out[(size_t)NN * 50 + (size_t)m * 15 + (j - 50)] = v + bfb[j - 50];
}

// ---------------- unified bf16 hi/lo mma GEMM ----------------
// C[M, NOUT] = A[M,128] @ B[NOUT,128]^T (+bias), 3 passes Ah*Bh + Ah*Bl + Al*Bh.
// 128x128 CTA tile; 8 warps 4m x 2n, each 32x64; smem stride 136 (ldmatrix conflict-free).

#define TSTRIDE 136
#define TILE_BYTES (128 * TSTRIDE * 2)   // 34816

__device__ __forceinline__ uint32_t smem_u32(const void* p) {
    uint32_t a;
    asm("{ .reg .u64 t; cvta.to.shared.u64 t, %1; cvt.u32.u64 %0, t; }" : "=r"(a) : "l"(p));
    return a;
}
__device__ __forceinline__ void ldsm_x4(uint32_t* r, uint32_t addr) {
    asm volatile("ldmatrix.sync.aligned.m8n8.x4.shared.b16 {%0,%1,%2,%3}, [%4];"
                 : "=r"(r[0]), "=r"(r[1]), "=r"(r[2]), "=r"(r[3]) : "r"(addr));
}
__device__ __forceinline__ void mma_bf16(float* d, const uint32_t* a, const uint32_t* b) {
    asm volatile(
        "mma.sync.aligned.m16n8k16.row.col.f32.bf16.bf16.f32 "
        "{%0,%1,%2,%3}, {%4,%5,%6,%7}, {%8,%9}, {%0,%1,%2,%3};"
        : "+f"(d[0]), "+f"(d[1]), "+f"(d[2]), "+f"(d[3])
        : "r"(a[0]), "r"(a[1]), "r"(a[2]), "r"(a[3]), "r"(b[0]), "r"(b[1]));
}
__device__ __forceinline__ void load_tile_bf16(char* dst, const __nv_bfloat16* __restrict__ src,
                                               int row0, int rowmax, int tid) {
    for (int i = tid; i < 2048; i += 256) {
        int r = i >> 4;
        int k = (i & 15) << 3;
        int gr = row0 + r;
        uint4 v = make_uint4(0, 0, 0, 0);
        if (gr < rowmax) v = *(const uint4*)(src + (size_t)gr * 128 + k);
        *(uint4*)(dst + ((size_t)r * TSTRIDE + k) * 2) = v;
    }
}

__global__ __launch_bounds__(256) void mma_gemm_kernel(
    const __nv_bfloat16* __restrict__ AH, const __nv_bfloat16* __restrict__ AL,
    const __nv_bfloat16* __restrict__ BH, const __nv_bfloat16* __restrict__ BL,
    const float* __restrict__ bias, float* __restrict__ outp, int M, int NOUT)
{
    extern __shared__ char smem[];
    char* sAh = smem;
    char* sAl = smem + TILE_BYTES;
    char* sBh = smem + 2 * TILE_BYTES;
    char* sBl = smem + 3 * TILE_BYTES;

    const int tid = threadIdx.x, wid = tid >> 5, lane = tid & 31;
    const int bm = blockIdx.y * 128;
    const int bn = blockIdx.x * 128;
    const int wm = (wid & 3) * 32;
    const int wn = (wid >> 2) * 64;

    load_tile_bf16(sAh, AH, bm, M, tid);
    load_tile_bf16(sAl, AL, bm, M, tid);
    load_tile_bf16(sBh, BH, bn, NOUT, tid);
    load_tile_bf16(sBl, BL, bn, NOUT, tid);
    __syncthreads();

    float acc[2][8][4];
#pragma unroll
    for (int mt = 0; mt < 2; mt++)
#pragma unroll
        for (int nt = 0; nt < 8; nt++)
#pragma unroll
            for (int q = 0; q < 4; q++) acc[mt][nt][q] = 0.f;

    const uint32_t aBase[3] = { smem_u32(sAh), smem_u32(sAh), smem_u32(sAl) };
    const uint32_t bBase[3] = { smem_u32(sBh), smem_u32(sBl), smem_u32(sBh) };

    const int a_row = wm + (lane & 15);
    const int a_col8 = (lane >> 4) * 8;
    const int b_row = wn + (lane & 7) + ((lane >> 4) & 1) * 8;
    const int b_col8 = ((lane >> 3) & 1) * 8;

#pragma unroll
    for (int p = 0; p < 3; p++) {
        const uint32_t ab = aBase[p];
        const uint32_t bb = bBase[p];
#pragma unroll
        for (int ks = 0; ks < 8; ks++) {
            uint32_t afr[2][4];
#pragma unroll
            for (int mt = 0; mt < 2; mt++) {
                uint32_t addr = ab + (uint32_t)(((a_row + mt * 16) * TSTRIDE) + ks * 16 + a_col8) * 2;
                ldsm_x4(afr[mt], addr);
            }
            uint32_t bfr[8][2];
#pragma unroll
            for (int np = 0; np < 4; np++) {
                uint32_t r[4];
                uint32_t addr = bb + (uint32_t)(((b_row + np * 16) * TSTRIDE) + ks * 16 + b_col8) * 2;
                ldsm_x4(r, addr);
                bfr[2 * np][0] = r[0]; bfr[2 * np][1] = r[1];
                bfr[2 * np + 1][0] = r[2]; bfr[2 * np + 1][1] = r[3];
            }
#pragma unroll
            for (int mt = 0; mt < 2; mt++)
#pragma unroll
                for (int nt = 0; nt < 8; nt++)
                    mma_bf16(acc[mt][nt], afr[mt], bfr[nt]);
        }
    }

    // epilogue: float2 only valid when NOUT is even (row stride 8B-aligned)
    const bool vec2 = ((NOUT & 1) == 0);
    const int g = lane >> 2, t = lane & 3;
#pragma unroll
    for (int mt = 0; mt < 2; mt++) {
        int m0 = bm + wm + mt * 16 + g;
#pragma unroll
        for (int nt = 0; nt < 8; nt++) {
            int n0 = bn + wn + nt * 8 + t * 2;
            if (n0 >= NOUT) continue;
            float bx = bias ? bias[n0] : 0.f;
            bool has2 = (n0 + 1 < NOUT);
            float by = (bias && has2) ? bias[n0 + 1] : 0.f;
            if (m0 < M) {
                float* p = outp + (size_t)m0 * NOUT + n0;
                if (has2 && vec2) *(float2*)p = make_float2(acc[mt][nt][0] + bx, acc[mt][nt][1] + by);
                else {
                    p[0] = acc[mt][nt][0] + bx;
                    if (has2) p[1] = acc[mt][nt][1] + by;
                }
            }
            if (m0 + 8 < M) {
                float* p = outp + (size_t)(m0 + 8) * NOUT + n0;
                if (has2 && vec2) *(float2*)p = make_float2(acc[mt][nt][2] + bx, acc[mt][nt][3] + by);
                else {
                    p[0] = acc[mt][nt][2] + bx;
                    if (has2) p[1] = acc[mt][nt][3] + by;
                }
            }
        }
    }
}

// ---------------- launch ----------------
extern "C" void kernel_launch(void* const* d_in, const int* in_sizes, int n_in,
                              void* d_out, int out_size) {
    const float* x  = (const float*)d_in[0];
    const int*   ei = (const int*)d_in[1];   // [2, NE] int32
    const float* W1 = (const float*)d_in[2];
    const float* b1 = (const float*)d_in[3];
    const float* W2 = (const float*)d_in[4];
    const float* b2 = (const float*)d_in[5];
    const float* Wt = (const float*)d_in[6];
    const float* bt = (const float*)d_in[7];
    const float* Ws = (const float*)d_in[8];
    const float* bs = (const float*)d_in[9];
    const float* Wf = (const float*)d_in[10];
    const float* bfb = (const float*)d_in[11];
    const float* Wa = (const float*)d_in[12];
    const float* ba = (const float*)d_in[13];
    float* out = (float*)d_out;

    float4* h4;
    float* csmall;
    __nv_bfloat16 *aH, *aL, *w1H, *w1L, *w2H, *w2L, *waH, *waL, *wsH, *wsL;
    cudaGetSymbolAddress((void**)&h4, g_h);
    cudaGetSymbolAddress((void**)&csmall, g_Csmall);
    cudaGetSymbolAddress((void**)&aH, g_AH);
    cudaGetSymbolAddress((void**)&aL, g_AL);
    cudaGetSymbolAddress((void**)&w1H, g_W1H);
    cudaGetSymbolAddress((void**)&w1L, g_W1L);
    cudaGetSymbolAddress((void**)&w2H, g_W2H);
    cudaGetSymbolAddress((void**)&w2L, g_W2L);
    cudaGetSymbolAddress((void**)&waH, g_WaH);
    cudaGetSymbolAddress((void**)&waL, g_WaL);
    cudaGetSymbolAddress((void**)&wsH, g_WsmH);
    cudaGetSymbolAddress((void**)&wsL, g_WsmL);

    static bool attr_set = false;
    if (!attr_set) {
        cudaFuncSetAttribute(mma_gemm_kernel,
                             cudaFuncAttributeMaxDynamicSharedMemorySize, 4 * TILE_BYTES);
        attr_set = true;
    }

    // normalization
    deg_init_kernel<<<(NN + 255) / 256, 256>>>();
    deg_accum_kernel<<<(NE + 255) / 256, 256>>>(ei);
    deg_rsqrt_kernel<<<(NN + 255) / 256, 256>>>();

    // conversions (independent)
    convert_x_kernel<<<(NN * 128 + 255) / 256, 256>>>(x);
    convert_W_kernel<<<(128 * 128 + 255) / 256, 256>>>(W1, 128, w1H, w1L);
    convert_W_kernel<<<(128 * 128 + 255) / 256, 256>>>(W2, 128, w2H, w2L);
    convert_W_kernel<<<(NAUTH * 128 + 255) / 256, 256>>>(Wa, NAUTH, waH, waL);
    pack_small_kernel<<<(NSMALL * 128 + 255) / 256, 256>>>(Wt, Ws, Wf);

    const int ELEM_BLK = (NN * 32 + 255) / 256;
    const int EDGE_BLK = ((NE * 32) + 255) / 256;
    const int MROWS = (NN + 127) / 128;   // 391

    // layer 1: h = x@W1 ; agg ; feat(hi/lo) = relu(agg + b1)
    mma_gemm_kernel<<<dim3(1, MROWS), 256, 4 * TILE_BYTES>>>(aH, aL, w1H, w1L, nullptr,
                                                             (float*)h4, NN, 128);
    init_agg_kernel<<<ELEM_BLK, 256>>>();
    edge_agg_kernel<<<EDGE_BLK, 256>>>(ei);
    finalize_kernel<1><<<ELEM_BLK, 256>>>(b1);

    // layer 2: h = feat@W2 ; agg ; emb(hi/lo) = agg + b2
    mma_gemm_kernel<<<dim3(1, MROWS), 256, 4 * TILE_BYTES>>>(aH, aL, w2H, w2L, nullptr,
                                                             (float*)h4, NN, 128);
    init_agg_kernel<<<ELEM_BLK, 256>>>();
    edge_agg_kernel<<<EDGE_BLK, 256>>>(ei);
    finalize_kernel<0><<<ELEM_BLK, 256>>>(b2);

    // small heads fused
    mma_gemm_kernel<<<dim3(1, MROWS), 256, 4 * TILE_BYTES>>>(aH, aL, wsH, wsL, nullptr,
                                                             csmall, NN, NSMALL);
    split_small_kernel<<<(NN * NSMALL + 255) / 256, 256>>>(bt, bs, bfb, out);

    // author head
    mma_gemm_kernel<<<dim3((NAUTH + 127) / 128, MROWS), 256, 4 * TILE_BYTES>>>(
        aH, aL, waH, waL, ba, out + (size_t)NN * 65, NN, NAUTH);
}

// round 8
// speedup vs baseline: 1.8013x; 1.1720x over previous
#include <cuda_runtime.h>
#include <cuda_bf16.h>
#include <cstdint>

#define NN 50000
#define CC 128
#define NE 800000
#define NAUTH 2000
#define NSMALL 65
#define NBLK ((NN + 1023) / 1024)   // 49 scan blocks

// ---------------- scratch (device globals; allocation-free rule) ----------------
__device__ float  g_dinv[NN];
__device__ int    g_cnt[NN];
__device__ int    g_scan[NN];
__device__ int    g_bsum[64];
__device__ int    g_rowptr[NN + 1];
__device__ int    g_cursor[NN];
__device__ int    g_col[NE];
__device__ float4 g_h[NN * 32];              // dense transform [NN][128]
__device__ __nv_bfloat16 g_AH[NN * 128];     // A operand hi (x, relu(h1), emb)
__device__ __nv_bfloat16 g_AL[NN * 128];     // A operand lo
__device__ __nv_bfloat16 g_WaH[NAUTH * 128]; // Wa^T [n][k]
__device__ __nv_bfloat16 g_WaL[NAUTH * 128];
__device__ __nv_bfloat16 g_W1H[128 * 128];
__device__ __nv_bfloat16 g_W1L[128 * 128];
__device__ __nv_bfloat16 g_W2H[128 * 128];
__device__ __nv_bfloat16 g_W2L[128 * 128];
__device__ __nv_bfloat16 g_WsmH[NSMALL * 128];
__device__ __nv_bfloat16 g_WsmL[NSMALL * 128];
__device__ float g_Csmall[NN * NSMALL];

// ---------------- CSR build ----------------
__global__ void zero_cnt_kernel() {
    int i = blockIdx.x * blockDim.x + threadIdx.x;
    if (i < NN) g_cnt[i] = 0;
}
__global__ void cnt_accum_kernel(const int* __restrict__ ei) {
    int e = blockIdx.x * blockDim.x + threadIdx.x;
    if (e < NE) atomicAdd(&g_cnt[ei[e]], 1);
}
// block-wise inclusive scan (1024/block)
__global__ void scan1_kernel() {
    int tid = threadIdx.x;
    int i = blockIdx.x * 1024 + tid;
    int lane = tid & 31, wid = tid >> 5;
    int v = (i < NN) ? g_cnt[i] : 0;
    int s = v;
#pragma unroll
    for (int o = 1; o < 32; o <<= 1) {
        int t = __shfl_up_sync(0xFFFFFFFFu, s, o);
        if (lane >= o) s += t;
    }
    __shared__ int wsum[32];
    if (lane == 31) wsum[wid] = s;
    __syncthreads();
    if (wid == 0) {
        int w = wsum[lane];
#pragma unroll
        for (int o = 1; o < 32; o <<= 1) {
            int t = __shfl_up_sync(0xFFFFFFFFu, w, o);
            if (lane >= o) w += t;
        }
        wsum[lane] = w;
    }
    __syncthreads();
    int inc = s + (wid > 0 ? wsum[wid - 1] : 0);
    if (i < NN) g_scan[i] = inc;
    if (tid == 1023) g_bsum[blockIdx.x] = inc;
}
__global__ void scan2_kernel() {
    __shared__ int s[64];
    int tid = threadIdx.x;
    s[tid] = (tid < NBLK) ? g_bsum[tid] : 0;
    __syncthreads();
    if (tid == 0) {
        int a = 0;
        for (int b = 0; b < NBLK; b++) { int t = s[b]; s[b] = a; a += t; }
    }
    __syncthreads();
    if (tid < NBLK) g_bsum[tid] = s[tid];
}
__global__ void scan3_kernel() {
    int i = blockIdx.x * blockDim.x + threadIdx.x;
    if (i >= NN) return;
    int ex = g_scan[i] - g_cnt[i] + g_bsum[i >> 10];
    g_rowptr[i] = ex;
    g_cursor[i] = ex;
    g_dinv[i] = rsqrtf((float)(g_cnt[i] + 1));   // +1 self loop
    if (i == 0) g_rowptr[NN] = NE;
}
__global__ void scatter_edges_kernel(const int* __restrict__ ei) {
    int e = blockIdx.x * blockDim.x + threadIdx.x;
    if (e >= NE) return;
    int r = ei[e], c = ei[NE + e];
    int pos = atomicAdd(&g_cursor[r], 1);
    g_col[pos] = c;
}

// ---------------- fused CSR aggregation + bias (+relu) + bf16 hi/lo ----------------
template <int RELU>
__global__ void csr_agg_kernel(const float* __restrict__ bias) {
    int w = (blockIdx.x * blockDim.x + threadIdx.x) >> 5;
    int lane = threadIdx.x & 31;
    if (w >= NN) return;
    int s = g_rowptr[w], t = g_rowptr[w + 1];
    float dd = g_dinv[w];
    float sc = dd * dd;
    float4 acc = g_h[(size_t)w * 32 + lane];
    acc.x *= sc; acc.y *= sc; acc.z *= sc; acc.w *= sc;
    for (int e = s; e < t; e++) {
        int c = g_col[e];                      // broadcast load
        float nm = dd * g_dinv[c];             // broadcast load
        float4 v = g_h[(size_t)c * 32 + lane];
        acc.x += v.x * nm; acc.y += v.y * nm; acc.z += v.z * nm; acc.w += v.w * nm;
    }
    float4 b = ((const float4*)bias)[lane];
    acc.x += b.x; acc.y += b.y; acc.z += b.z; acc.w += b.w;
    if (RELU) {
        acc.x = fmaxf(acc.x, 0.f); acc.y = fmaxf(acc.y, 0.f);
        acc.z = fmaxf(acc.z, 0.f); acc.w = fmaxf(acc.w, 0.f);
    }
    float f[4] = {acc.x, acc.y, acc.z, acc.w};
    __nv_bfloat16 hi[4], lo[4];
#pragma unroll
    for (int q = 0; q < 4; q++) {
        hi[q] = __float2bfloat16(f[q]);
        lo[q] = __float2bfloat16(f[q] - __bfloat162float(hi[q]));
    }
    size_t idx = ((size_t)w * 32 + lane) * 4;
    *(uint2*)(g_AH + idx) = *(uint2*)hi;
    *(uint2*)(g_AL + idx) = *(uint2*)lo;
}

// ---------------- conversions ----------------
__global__ void convert_x_kernel(const float* __restrict__ x) {
    int i = blockIdx.x * blockDim.x + threadIdx.x;   // over NN*32 float4s
    if (i >= NN * 32) return;
    float4 v = ((const float4*)x)[i];
    float f[4] = {v.x, v.y, v.z, v.w};
    __nv_bfloat16 hi[4], lo[4];
#pragma unroll
    for (int q = 0; q < 4; q++) {
        hi[q] = __float2bfloat16(f[q]);
        lo[q] = __float2bfloat16(f[q] - __bfloat162float(hi[q]));
    }
    *(uint2*)(g_AH + (size_t)i * 4) = *(uint2*)hi;
    *(uint2*)(g_AL + (size_t)i * 4) = *(uint2*)lo;
}
__global__ void convert_W_kernel(const float* __restrict__ W, int N,
                                 __nv_bfloat16* __restrict__ dH, __nv_bfloat16* __restrict__ dL) {
    int i = blockIdx.x * blockDim.x + threadIdx.x;
    if (i >= N * 128) return;
    int n = i >> 7, k = i & 127;
    float f = W[(size_t)k * N + n];
    __nv_bfloat16 hi = __float2bfloat16(f);
    dH[i] = hi;
    dL[i] = __float2bfloat16(f - __bfloat162float(hi));
}
__global__ void pack_small_kernel(const float* __restrict__ Wt, const float* __restrict__ Ws,
                                  const float* __restrict__ Wf) {
    int i = blockIdx.x * blockDim.x + threadIdx.x;
    if (i >= NSMALL * 128) return;
    int j = i >> 7, k = i & 127;
    float v;
    if (j < 30)      v = Wt[(size_t)k * 30 + j];
    else if (j < 50) v = Ws[(size_t)k * 20 + (j - 30)];
    else             v = Wf[(size_t)k * 15 + (j - 50)];
    __nv_bfloat16 hi = __float2bfloat16(v);
    g_WsmH[i] = hi;
    g_WsmL[i] = __float2bfloat16(v - __bfloat162float(hi));
}
__global__ void split_small_kernel(const float* __restrict__ bt, const float* __restrict__ bs,
                                   const float* __restrict__ bfb, float* __restrict__ out) {
    int i = blockIdx.x * blockDim.x + threadIdx.x;
    if (i >= NN * NSMALL) return;
    int m = i / NSMALL, j = i % NSMALL;
    float v = g_Csmall[i];
    if (j < 30)      out[(size_t)m * 30 + j] = v + bt[j];
    else if (j < 50) out[(size_t)NN * 30 + (size_t)m * 20 + (j - 30)] = v + bs[j - 30];
    else             out[(size_t)NN * 50 + (size_t)m * 15 + (j - 50)] = v + bfb[j - 50];
}

// ---------------- unified bf16 hi/lo mma GEMM ----------------
#define TSTRIDE 136
#define TILE_BYTES (128 * TSTRIDE * 2)

__device__ __forceinline__ uint32_t smem_u32(const void* p) {
    uint32_t a;
    asm("{ .reg .u64 t; cvta.to.shared.u64 t, %1; cvt.u32.u64 %0, t; }" : "=r"(a) : "l"(p));
    return a;
}
__device__ __forceinline__ void ldsm_x4(uint32_t* r, uint32_t addr) {
    asm volatile("ldmatrix.sync.aligned.m8n8.x4.shared.b16 {%0,%1,%2,%3}, [%4];"
                 : "=r"(r[0]), "=r"(r[1]), "=r"(r[2]), "=r"(r[3]) : "r"(addr));
}
__device__ __forceinline__ void mma_bf16(float* d, const uint32_t* a, const uint32_t* b) {
    asm volatile(
        "mma.sync.aligned.m16n8k16.row.col.f32.bf16.bf16.f32 "
        "{%0,%1,%2,%3}, {%4,%5,%6,%7}, {%8,%9}, {%0,%1,%2,%3};"
        : "+f"(d[0]), "+f"(d[1]), "+f"(d[2]), "+f"(d[3])
        : "r"(a[0]), "r"(a[1]), "r"(a[2]), "r"(a[3]), "r"(b[0]), "r"(b[1]));
}
__device__ __forceinline__ void load_tile_bf16(char* dst, const __nv_bfloat16* __restrict__ src,
                                               int row0, int rowmax, int tid) {
    for (int i = tid; i < 2048; i += 256) {
        int r = i >> 4;
        int k = (i & 15) << 3;
        int gr = row0 + r;
        uint4 v = make_uint4(0, 0, 0, 0);
        if (gr < rowmax) v = *(const uint4*)(src + (size_t)gr * 128 + k);
        *(uint4*)(dst + ((size_t)r * TSTRIDE + k) * 2) = v;
    }
}

__global__ __launch_bounds__(256) void mma_gemm_kernel(
    const __nv_bfloat16* __restrict__ AH, const __nv_bfloat16* __restrict__ AL,
    const __nv_bfloat16* __restrict__ BH, const __nv_bfloat16* __restrict__ BL,
    const float* __restrict__ bias, float* __restrict__ outp, int M, int NOUT)
{
    extern __shared__ char smem[];
    char* sAh = smem;
    char* sAl = smem + TILE_BYTES;
    char* sBh = smem + 2 * TILE_BYTES;
    char* sBl = smem + 3 * TILE_BYTES;

    const int tid = threadIdx.x, wid = tid >> 5, lane = tid & 31;
    const int bm = blockIdx.y * 128;
    const int bn = blockIdx.x * 128;
    const int wm = (wid & 3) * 32;
    const int wn = (wid >> 2) * 64;

    load_tile_bf16(sAh, AH, bm, M, tid);
    load_tile_bf16(sAl, AL, bm, M, tid);
    load_tile_bf16(sBh, BH, bn, NOUT, tid);
    load_tile_bf16(sBl, BL, bn, NOUT, tid);
    __syncthreads();

    float acc[2][8][4];
#pragma unroll
    for (int mt = 0; mt < 2; mt++)
#pragma unroll
        for (int nt = 0; nt < 8; nt++)
#pragma unroll
            for (int q = 0; q < 4; q++) acc[mt][nt][q] = 0.f;

    const uint32_t aBase[3] = { smem_u32(sAh), smem_u32(sAh), smem_u32(sAl) };
    const uint32_t bBase[3] = { smem_u32(sBh), smem_u32(sBl), smem_u32(sBh) };

    const int a_row = wm + (lane & 15);
    const int a_col8 = (lane >> 4) * 8;
    const int b_row = wn + (lane & 7) + ((lane >> 4) & 1) * 8;
    const int b_col8 = ((lane >> 3) & 1) * 8;

#pragma unroll
    for (int p = 0; p < 3; p++) {
        const uint32_t ab = aBase[p];
        const uint32_t bb = bBase[p];
#pragma unroll
        for (int ks = 0; ks < 8; ks++) {
            uint32_t afr[2][4];
#pragma unroll
            for (int mt = 0; mt < 2; mt++) {
                uint32_t addr = ab + (uint32_t)(((a_row + mt * 16) * TSTRIDE) + ks * 16 + a_col8) * 2;
                ldsm_x4(afr[mt], addr);
            }
            uint32_t bfr[8][2];
#pragma unroll
            for (int np = 0; np < 4; np++) {
                uint32_t r[4];
                uint32_t addr = bb + (uint32_t)(((b_row + np * 16) * TSTRIDE) + ks * 16 + b_col8) * 2;
                ldsm_x4(r, addr);
                bfr[2 * np][0] = r[0]; bfr[2 * np][1] = r[1];
                bfr[2 * np + 1][0] = r[2]; bfr[2 * np + 1][1] = r[3];
            }
#pragma unroll
            for (int mt = 0; mt < 2; mt++)
#pragma unroll
                for (int nt = 0; nt < 8; nt++)
                    mma_bf16(acc[mt][nt], afr[mt], bfr[nt]);
        }
    }

    const bool vec2 = ((NOUT & 1) == 0);
    const int g = lane >> 2, t = lane & 3;
#pragma unroll
    for (int mt = 0; mt < 2; mt++) {
        int m0 = bm + wm + mt * 16 + g;
#pragma unroll
        for (int nt = 0; nt < 8; nt++) {
            int n0 = bn + wn + nt * 8 + t * 2;
            if (n0 >= NOUT) continue;
            float bx = bias ? bias[n0] : 0.f;
            bool has2 = (n0 + 1 < NOUT);
            float by = (bias && has2) ? bias[n0 + 1] : 0.f;
            if (m0 < M) {
                float* p = outp + (size_t)m0 * NOUT + n0;
                if (has2 && vec2) *(float2*)p = make_float2(acc[mt][nt][0] + bx, acc[mt][nt][1] + by);
                else {
                    p[0] = acc[mt][nt][0] + bx;
                    if (has2) p[1] = acc[mt][nt][1] + by;
                }
            }
            if (m0 + 8 < M) {
                float* p = outp + (size_t)(m0 + 8) * NOUT + n0;
                if (has2 && vec2) *(float2*)p = make_float2(acc[mt][nt][2] + bx, acc[mt][nt][3] + by);
                else {
                    p[0] = acc[mt][nt][2] + bx;
                    if (has2) p[1] = acc[mt][nt][3] + by;
                }
            }
        }
    }
}

// ---------------- launch ----------------
extern "C" void kernel_launch(void* const* d_in, const int* in_sizes, int n_in,
                              void* d_out, int out_size) {
    const float* x  = (const float*)d_in[0];
    const int*   ei = (const int*)d_in[1];   // [2, NE] int32
    const float* W1 = (const float*)d_in[2];
    const float* b1 = (const float*)d_in[3];
    const float* W2 = (const float*)d_in[4];
    const float* b2 = (const float*)d_in[5];
    const float* Wt = (const float*)d_in[6];
    const float* bt = (const float*)d_in[7];
    const float* Ws = (const float*)d_in[8];
    const float* bs = (const float*)d_in[9];
    const float* Wf = (const float*)d_in[10];
    const float* bfb = (const float*)d_in[11];
    const float* Wa = (const float*)d_in[12];
    const float* ba = (const float*)d_in[13];
    float* out = (float*)d_out;

    float4* h4;
    float* csmall;
    __nv_bfloat16 *aH, *aL, *w1H, *w1L, *w2H, *w2L, *waH, *waL, *wsH, *wsL;
    cudaGetSymbolAddress((void**)&h4, g_h);
    cudaGetSymbolAddress((void**)&csmall, g_Csmall);
    cudaGetSymbolAddress((void**)&aH, g_AH);
    cudaGetSymbolAddress((void**)&aL, g_AL);
    cudaGetSymbolAddress((void**)&w1H, g_W1H);
    cudaGetSymbolAddress((void**)&w1L, g_W1L);
    cudaGetSymbolAddress((void**)&w2H, g_W2H);
    cudaGetSymbolAddress((void**)&w2L, g_W2L);
    cudaGetSymbolAddress((void**)&waH, g_WaH);
    cudaGetSymbolAddress((void**)&waL, g_WaL);
    cudaGetSymbolAddress((void**)&wsH, g_WsmH);
    cudaGetSymbolAddress((void**)&wsL, g_WsmL);

    static bool attr_set = false;
    if (!attr_set) {
        cudaFuncSetAttribute(mma_gemm_kernel,
                             cudaFuncAttributeMaxDynamicSharedMemorySize, 4 * TILE_BYTES);
        attr_set = true;
    }

    // CSR build (shared by both conv layers)
    zero_cnt_kernel<<<(NN + 255) / 256, 256>>>();
    cnt_accum_kernel<<<(NE + 255) / 256, 256>>>(ei);
    scan1_kernel<<<NBLK, 1024>>>();
    scan2_kernel<<<1, 64>>>();
    scan3_kernel<<<(NN + 255) / 256, 256>>>();
    scatter_edges_kernel<<<(NE + 255) / 256, 256>>>(ei);

    // conversions
    convert_x_kernel<<<(NN * 32 + 255) / 256, 256>>>(x);
    convert_W_kernel<<<(128 * 128 + 255) / 256, 256>>>(W1, 128, w1H, w1L);
    convert_W_kernel<<<(128 * 128 + 255) / 256, 256>>>(W2, 128, w2H, w2L);
    convert_W_kernel<<<(NAUTH * 128 + 255) / 256, 256>>>(Wa, NAUTH, waH, waL);
    pack_small_kernel<<<(NSMALL * 128 + 255) / 256, 256>>>(Wt, Ws, Wf);

    const int AGG_BLK = (NN * 32 + 255) / 256;
    const int MROWS = (NN + 127) / 128;   // 391

    // layer 1
    mma_gemm_kernel<<<dim3(1, MROWS), 256, 4 * TILE_BYTES>>>(aH, aL, w1H, w1L, nullptr,
                                                             (float*)h4, NN, 128);
    csr_agg_kernel<1><<<AGG_BLK, 256>>>(b1);

    // layer 2
    mma_gemm_kernel<<<dim3(1, MROWS), 256, 4 * TILE_BYTES>>>(aH, aL, w2H, w2L, nullptr,
                                                             (float*)h4, NN, 128);
    csr_agg_kernel<0><<<AGG_BLK, 256>>>(b2);

    // small heads fused
    mma_gemm_kernel<<<dim3(1, MROWS), 256, 4 * TILE_BYTES>>>(aH, aL, wsH, wsL, nullptr,
                                                             csmall, NN, NSMALL);
    split_small_kernel<<<(NN * NSMALL + 255) / 256, 256>>>(bt, bs, bfb, out);

    // author head
    mma_gemm_kernel<<<dim3((NAUTH + 127) / 128, MROWS), 256, 4 * TILE_BYTES>>>(
        aH, aL, waH, waL, ba, out + (size_t)NN * 65, NN, NAUTH);
}